// round 16
// baseline (speedup 1.0000x reference)
#include <cuda_runtime.h>
#include <cuda_bf16.h>

#define BB 8
#define CC 96
#define C3 288
#define HH 192
#define WW 192
#define HWP (HH*WW)
#define NH 3
#define HD 32
#define NCHUNK 32
#define CHUNK (HWP/NCHUNK)   // 1152
#define PXT 128
#define NPXT (HWP/PXT)       // 288
#define SP 136               // act smem stride in u32 words (ch-pair rows)

typedef unsigned long long u64;
typedef unsigned int u32;

// ---------------- scratch ----------------
__device__ __nv_bfloat16 g_qkv [(size_t)BB*C3*HWP];   // q,k only (ch 0..191)
__device__ __nv_bfloat16 g_qkvd[(size_t)BB*C3*HWP];   // dw(q,k) (ch 0..191)
__device__ u32   g_vp_in[(size_t)BB*48*HWP];          // v pre-dw, ch-pair packed
__device__ u32   g_vp   [(size_t)BB*48*HWP];          // dw(v), ch-pair packed
__device__ float g_Sp  [NCHUNK*BB*NH*HD*HD];
__device__ float g_sqp [NCHUNK*BB*192];
__device__ u32   g_Wp  [BB*36*128];
__device__ u32 g_pk_qkv [108*128];
__device__ u32 g_pk_proj[36*128];
__device__ u32 g_pk_c1  [72*128];
__device__ u32 g_pk_c2  [36*128];

// ---------------- helpers ----------------
__device__ __forceinline__ void mma16(float d[4], const u32 a[4], u32 b0, u32 b1) {
    asm volatile(
        "mma.sync.aligned.m16n8k16.row.col.f32.bf16.bf16.f32 "
        "{%0,%1,%2,%3},{%4,%5,%6,%7},{%8,%9},{%0,%1,%2,%3};"
        : "+f"(d[0]), "+f"(d[1]), "+f"(d[2]), "+f"(d[3])
        : "r"(a[0]), "r"(a[1]), "r"(a[2]), "r"(a[3]), "r"(b0), "r"(b1));
}
__device__ __forceinline__ void ldAb(u32 a[4], const u32* pk, int frag, int lane) {
    uint4 f = *(const uint4*)(pk + (size_t)frag*128 + lane*4);
    a[0] = f.x; a[1] = f.y; a[2] = f.z; a[3] = f.w;
}
__device__ __forceinline__ u32 packbf(float lo, float hi) {
    __nv_bfloat162 t = __float22bfloat162_rn(make_float2(lo, hi));
    return *reinterpret_cast<u32*>(&t);
}
__device__ __forceinline__ void stbf(u32* buf, int r, int p, float v) {
    reinterpret_cast<__nv_bfloat16*>(buf)[(r >> 1)*(SP*2) + p*2 + (r & 1)] =
        __float2bfloat16(v);
}
__device__ __forceinline__ float2 unbf(u32 wv) {
    __nv_bfloat162 h = *reinterpret_cast<__nv_bfloat162*>(&wv);
    return __bfloat1622float2(h);
}
__device__ __forceinline__ float lobf(u32 v) { return __uint_as_float(v << 16); }
__device__ __forceinline__ float hibf(u32 v) { return __uint_as_float(v & 0xFFFF0000u); }
// f32x2 packed helpers (FFMA2: two independent FMAs, bitwise-identical rounding)
__device__ __forceinline__ u64 pack2(float a, float b) {
    u64 r; asm("mov.b64 %0, {%1, %2};" : "=l"(r) : "f"(a), "f"(b)); return r;
}
__device__ __forceinline__ void fma2(u64& d, u64 a, u64 b) {
    asm("fma.rn.f32x2 %0, %1, %2, %0;" : "+l"(d) : "l"(a), "l"(b));
}
__device__ __forceinline__ float2 unpk2(u64 v) {
    float2 r; asm("mov.b64 {%0, %1}, %2;" : "=f"(r.x), "=f"(r.y) : "l"(v)); return r;
}
__device__ __forceinline__ u32 s2u(const void* p) {
    u32 a;
    asm("{ .reg .u64 t; cvta.to.shared.u64 t, %1; cvt.u32.u64 %0, t; }"
        : "=r"(a) : "l"(p));
    return a;
}
__device__ __forceinline__ void cpa16(u32 d, const void* s) {
    asm volatile("cp.async.cg.shared.global [%0], [%1], 16;" :: "r"(d), "l"(s));
}
__device__ __forceinline__ void cpa8(u32 d, const void* s) {
    asm volatile("cp.async.ca.shared.global [%0], [%1], 8;" :: "r"(d), "l"(s));
}
#define CPA_COMMIT() asm volatile("cp.async.commit_group;")
#define CPA_WAIT(n)  asm volatile("cp.async.wait_group %0;" :: "n"(n))

// ============ K0: pack weights into bf16 A-fragment order ============
__global__ void k0_pack(const float* __restrict__ qkvw, const float* __restrict__ projw,
                        const float* __restrict__ c1w,  const float* __restrict__ c2w)
{
    int e = blockIdx.x*256 + threadIdx.x;
    const float* src; u32* dst; int idx = e;
    if      (idx < 13824) { src = qkvw; dst = g_pk_qkv; }
    else if (idx < 18432) { idx -= 13824; src = projw; dst = g_pk_proj; }
    else if (idx < 27648) { idx -= 18432; src = c1w;  dst = g_pk_c1; }
    else if (idx < 32256) { idx -= 27648; src = c2w;  dst = g_pk_c2; }
    else return;
    int f = idx >> 7, rem = idx & 127;
    int lane = rem >> 2, q = rem & 3;
    int mt = f / 6, s = f % 6;
    int g = lane >> 2, tig = lane & 3;
    int r  = mt*16 + g + (q & 1)*8;
    int kb = s*16 + 2*tig + (q >> 1)*8;
    dst[idx] = packbf(src[r*96 + kb], src[r*96 + kb + 1]);
}

// ============ K1: LN1 + qkv (bf16 mma; q,k normal, v packed ch-pair) ============
__global__ void __launch_bounds__(256) k1_ln_qkv(
    const float* __restrict__ x,    const float* __restrict__ ln1w,
    const float* __restrict__ ln1b, const float* __restrict__ qkvb)
{
    extern __shared__ __align__(16) u32 smu[];   // 48*SP input + 2 x 32*66 staging
    u32* stg = smu + 48*SP;
    int b  = blockIdx.x / NPXT;
    int p0 = (blockIdx.x % NPXT) * PXT;
    int tid = threadIdx.x;

    const float* xb = x + (size_t)b*CC*HWP + p0;
    for (int idx = tid; idx < 48*32; idx += 256) {
        int c2 = idx >> 5, p4 = (idx & 31)*4;
        float4 v0 = __ldcs((const float4*)(xb + (size_t)(2*c2)*HWP + p4));
        float4 v1 = __ldcs((const float4*)(xb + (size_t)(2*c2 + 1)*HWP + p4));
        smu[c2*SP + p4 + 0] = packbf(v0.x, v1.x);
        smu[c2*SP + p4 + 1] = packbf(v0.y, v1.y);
        smu[c2*SP + p4 + 2] = packbf(v0.z, v1.z);
        smu[c2*SP + p4 + 3] = packbf(v0.w, v1.w);
    }
    __syncthreads();
    {
        int px = tid >> 1, half = tid & 1;
        int c20 = half * 24;
        float s = 0.f, s2 = 0.f;
        #pragma unroll
        for (int c2 = c20; c2 < c20 + 24; c2++) {
            float2 f = unbf(smu[c2*SP + px]);
            s += f.x + f.y; s2 += f.x*f.x + f.y*f.y;
        }
        s  += __shfl_xor_sync(0xffffffffu, s, 1);
        s2 += __shfl_xor_sync(0xffffffffu, s2, 1);
        float mu  = s * (1.0f/96.0f);
        float var = fmaxf(s2 * (1.0f/96.0f) - mu*mu, 0.f);
        float rs  = rsqrtf(var + 1e-6f);
        #pragma unroll
        for (int c2 = c20; c2 < c20 + 24; c2++) {
            float2 f = unbf(smu[c2*SP + px]);
            float y0 = (f.x - mu)*rs*ln1w[2*c2]   + ln1b[2*c2];
            float y1 = (f.y - mu)*rs*ln1w[2*c2+1] + ln1b[2*c2+1];
            smu[c2*SP + px] = packbf(y0, y1);
        }
    }
    __syncthreads();

    int w = tid >> 5, lane = tid & 31;
    int g = lane >> 2, tig = lane & 3;
    int pxw = w * 16;
    #pragma unroll 1
    for (int mtp = 0; mtp < 9; mtp++) {
        u32* stgp = stg + (mtp & 1)*(32*66);
        float D[2][2][4];
        #pragma unroll
        for (int m = 0; m < 2; m++)
            #pragma unroll
            for (int n = 0; n < 2; n++)
                #pragma unroll
                for (int c = 0; c < 4; c++) D[m][n][c] = 0.f;
        #pragma unroll
        for (int s = 0; s < 6; s++) {
            u32 A0[4], A1[4];
            ldAb(A0, g_pk_qkv, (2*mtp)*6 + s, lane);
            ldAb(A1, g_pk_qkv, (2*mtp + 1)*6 + s, lane);
            u32 b00 = smu[(8*s + tig)*SP + pxw + g];
            u32 b01 = smu[(8*s + tig + 4)*SP + pxw + g];
            u32 b10 = smu[(8*s + tig)*SP + pxw + 8 + g];
            u32 b11 = smu[(8*s + tig + 4)*SP + pxw + 8 + g];
            mma16(D[0][0], A0, b00, b01); mma16(D[0][1], A0, b10, b11);
            mma16(D[1][0], A1, b00, b01); mma16(D[1][1], A1, b10, b11);
        }
        #pragma unroll
        for (int m = 0; m < 2; m++) {
            int r0 = (2*mtp + m)*16 + g;
            int lr = m*16 + g;
            float bz0 = qkvb[r0], bz1 = qkvb[r0 + 8];
            #pragma unroll
            for (int n = 0; n < 2; n++) {
                int cw = (pxw >> 1) + n*4 + tig;
                stgp[lr*66 + cw]       = packbf(D[m][n][0] + bz0, D[m][n][1] + bz0);
                stgp[(lr + 8)*66 + cw] = packbf(D[m][n][2] + bz1, D[m][n][3] + bz1);
            }
        }
        __syncthreads();
        if (mtp < 6) {
            int rowbase = mtp*32;
            #pragma unroll
            for (int it = 0; it < 4; it++) {
                int idx = tid + it*256;
                int r = idx >> 5, cw2 = (idx & 31) * 2;
                *(uint2*)((u32*)(g_qkv + ((size_t)b*C3 + rowbase + r)*HWP + p0) + cw2) =
                    *(const uint2*)(stgp + r*66 + cw2);
            }
        } else {
            int c2base = (mtp - 6)*16;
            #pragma unroll
            for (int it = 0; it < 4; it++) {
                int idx = tid + it*256;
                int a = idx >> 6, j2 = idx & 63;
                u32 w0 = stgp[(2*a)*66 + j2];
                u32 w1 = stgp[(2*a + 1)*66 + j2];
                uint2 o;
                o.x = __byte_perm(w0, w1, 0x5410);
                o.y = __byte_perm(w0, w1, 0x7632);
                *(uint2*)(g_vp_in + ((size_t)(b*48 + c2base + a))*HWP + p0 + 2*j2) = o;
            }
        }
    }
}

// ============ K2: merged depthwise 3x3 (q,k pairs + packed v), FFMA2 ============
__global__ void __launch_bounds__(192) k2_dw(const float* __restrict__ dww,
                                             const float* __restrict__ dwb)
{
    __shared__ u32 sm2[2*34*100];   // qk: [cc][34][100]; v: [34][196] (fits)
    int bx = blockIdx.x;
    int y0 = blockIdx.y * 32;
    int tid = threadIdx.x;

    if (bx < BB*96) {
        // ---- q,k path: 2 channels, thread = (half=ch, t=px-pair) ----
        int b = bx / 96, chp = bx % 96;
        int ch0 = 2*chp;
        int half = tid / 96, t = tid % 96;
        for (int idx = tid; idx < 2*34*48; idx += 192) {
            int cc = idx / 1632, rem = idx % 1632;
            int r = rem / 48, q2 = rem % 48;
            int y = y0 - 1 + r;
            u32* dsts = sm2 + cc*3400 + r*100 + q2*2;
            if (y >= 0 && y < HH) {
                const __nv_bfloat16* in = g_qkv + ((size_t)b*C3 + ch0 + cc)*HWP;
                cpa8(s2u(dsts), (const u32*)(in + y*WW) + q2*2);
            } else {
                dsts[0] = 0u; dsts[1] = 0u;
            }
        }
        CPA_COMMIT();
        CPA_WAIT(0);
        __syncthreads();

        int ch = ch0 + half;
        u64 w2[9];
        #pragma unroll
        for (int q = 0; q < 9; q++) {
            float wq = dww[ch*9 + q];
            w2[q] = pack2(wq, wq);
        }
        u64 bias2 = pack2(dwb[ch], dwb[ch]);
        u32* outw = (u32*)(g_qkvd + ((size_t)b*C3 + ch)*HWP);
        const u32* base = sm2 + half*3400;
        bool hasL = (t > 0), hasR = (t < 95);

        u64 P0[3], P1[3], P2[3];   // (a,b), (b,c), (c,d) column pairs per row slot
        #pragma unroll
        for (int r = 0; r < 2; r++) {
            const u32* rowp = base + r*100;
            u32 wp = hasL ? rowp[t-1] : 0u;
            u32 wm = rowp[t];
            u32 wn = hasR ? rowp[t+1] : 0u;
            float a = hibf(wp), bb = lobf(wm), c = hibf(wm), d = lobf(wn);
            P0[r] = pack2(a, bb); P1[r] = pack2(bb, c); P2[r] = pack2(c, d);
        }
        #pragma unroll
        for (int ry = 0; ry < 32; ry++) {
            int s2 = (ry + 2) % 3;
            {
                const u32* rowp = base + (ry + 2)*100;
                u32 wp = hasL ? rowp[t-1] : 0u;
                u32 wm = rowp[t];
                u32 wn = hasR ? rowp[t+1] : 0u;
                float a = hibf(wp), bb = lobf(wm), c = hibf(wm), d = lobf(wn);
                P0[s2] = pack2(a, bb); P1[s2] = pack2(bb, c); P2[s2] = pack2(c, d);
            }
            int s0 = ry % 3, s1 = (ry + 1) % 3;
            u64 acc = bias2;
            fma2(acc, w2[0], P0[s0]); fma2(acc, w2[1], P1[s0]); fma2(acc, w2[2], P2[s0]);
            fma2(acc, w2[3], P0[s1]); fma2(acc, w2[4], P1[s1]); fma2(acc, w2[5], P2[s1]);
            fma2(acc, w2[6], P0[s2]); fma2(acc, w2[7], P1[s2]); fma2(acc, w2[8], P2[s2]);
            float2 o = unpk2(acc);
            outw[(y0 + ry)*96 + t] = packbf(o.x, o.y);
        }
    } else {
        // ---- v path: 1 ch-pair word per pixel, thread = pixel ----
        int vx = bx - BB*96;
        int b = vx / 48, c2 = vx % 48;
        const u32* inw = g_vp_in + (size_t)(b*48 + c2)*HWP;
        for (int idx = tid; idx < 34*96; idx += 192) {
            int r = idx / 96, q2 = idx % 96;
            int y = y0 - 1 + r;
            u32* d = sm2 + r*196 + q2*2;
            if (y >= 0 && y < HH) cpa8(s2u(d), inw + y*WW + q2*2);
            else { d[0] = 0u; d[1] = 0u; }
        }
        CPA_COMMIT();
        CPA_WAIT(0);
        __syncthreads();

        int ch0 = 192 + 2*c2;
        u64 wq2[9];
        #pragma unroll
        for (int q = 0; q < 9; q++)
            wq2[q] = pack2(dww[ch0*9 + q], dww[(ch0+1)*9 + q]);
        u64 bias2 = pack2(dwb[ch0], dwb[ch0 + 1]);
        u32* outw = g_vp + (size_t)(b*48 + c2)*HWP;
        int t = tid;
        bool hasL = (t > 0), hasR = (t < WW - 1);

        u64 L[3], M[3], N[3];   // (ch0,ch1) value pairs per row slot
        #pragma unroll
        for (int r = 0; r < 2; r++) {
            const u32* rp = sm2 + r*196;
            u32 wl = hasL ? rp[t-1] : 0u;
            u32 wm = rp[t];
            u32 wn = hasR ? rp[t+1] : 0u;
            L[r] = pack2(lobf(wl), hibf(wl));
            M[r] = pack2(lobf(wm), hibf(wm));
            N[r] = pack2(lobf(wn), hibf(wn));
        }
        #pragma unroll
        for (int ry = 0; ry < 32; ry++) {
            int s2 = (ry + 2) % 3;
            {
                const u32* rp = sm2 + (ry + 2)*196;
                u32 wl = hasL ? rp[t-1] : 0u;
                u32 wm = rp[t];
                u32 wn = hasR ? rp[t+1] : 0u;
                L[s2] = pack2(lobf(wl), hibf(wl));
                M[s2] = pack2(lobf(wm), hibf(wm));
                N[s2] = pack2(lobf(wn), hibf(wn));
            }
            int s0 = ry % 3, s1 = (ry + 1) % 3;
            u64 acc = bias2;
            fma2(acc, wq2[0], L[s0]); fma2(acc, wq2[1], M[s0]); fma2(acc, wq2[2], N[s0]);
            fma2(acc, wq2[3], L[s1]); fma2(acc, wq2[4], M[s1]); fma2(acc, wq2[5], N[s1]);
            fma2(acc, wq2[6], L[s2]); fma2(acc, wq2[7], M[s2]); fma2(acc, wq2[8], N[s2]);
            float2 o = unpk2(acc);
            outw[(y0 + ry)*WW + t] = packbf(o.x, o.y);
        }
    }
}

// ============ K3: Gram + sumsq, bf16 mma, cp.async double-buffered ============
__global__ void __launch_bounds__(256) k3_gram()
{
    extern __shared__ __align__(16) u32 qk2[];
    __shared__ float ssq[8][32];
    int bh = blockIdx.x, chunk = blockIdx.y;
    int b = bh / NH, h = bh % NH;
    int tid = threadIdx.x;
    int w = tid >> 5, lane = tid & 31;
    int g = lane >> 2, tig = lane & 3;
    const __nv_bfloat16* qbase = g_qkvd + ((size_t)b*C3 + h*HD)*HWP + chunk*CHUNK;
    const __nv_bfloat16* kbase = g_qkvd + ((size_t)b*C3 + 96 + h*HD)*HWP + chunk*CHUNK;

    float D[2][4][4];
    #pragma unroll
    for (int m = 0; m < 2; m++)
        #pragma unroll
        for (int n = 0; n < 4; n++)
            #pragma unroll
            for (int c = 0; c < 4; c++) D[m][n][c] = 0.f;
    float acc = 0.f;
    int wq = (w & 3) * 16;

    {
        #pragma unroll
        for (int it = 0; it < 2; it++) {
            int idx = tid + it*256;
            int ci = idx >> 4, w4 = (idx & 15)*4;
            cpa16(s2u(qk2 + ci*68 + w4),
                  (const u32*)(qbase + (size_t)ci*HWP) + w4);
            cpa16(s2u(qk2 + 2176 + ci*68 + w4),
                  (const u32*)(kbase + (size_t)ci*HWP) + w4);
        }
        CPA_COMMIT();
    }

    #pragma unroll 1
    for (int st = 0; st < 9; st++) {
        u32* cur = qk2 + (st & 1)*4352;
        if (st < 8) {
            u32* nxt = qk2 + ((st + 1) & 1)*4352;
            int poff = (st + 1)*128;
            #pragma unroll
            for (int it = 0; it < 2; it++) {
                int idx = tid + it*256;
                int ci = idx >> 4, w4 = (idx & 15)*4;
                cpa16(s2u(nxt + ci*68 + w4),
                      (const u32*)(qbase + (size_t)ci*HWP + poff) + w4);
                cpa16(s2u(nxt + 2176 + ci*68 + w4),
                      (const u32*)(kbase + (size_t)ci*HWP + poff) + w4);
            }
            CPA_COMMIT();
            CPA_WAIT(1);
        } else {
            CPA_WAIT(0);
        }
        __syncthreads();
        u32* qs = cur;
        u32* ks = cur + 2176;
        {
            u32 A[2][4];
            #pragma unroll
            for (int m = 0; m < 2; m++) {
                A[m][0] = qs[(m*16 + g)*68     + w*8 + tig];
                A[m][1] = qs[(m*16 + g + 8)*68 + w*8 + tig];
                A[m][2] = qs[(m*16 + g)*68     + w*8 + tig + 4];
                A[m][3] = qs[(m*16 + g + 8)*68 + w*8 + tig + 4];
            }
            #pragma unroll
            for (int n = 0; n < 4; n++) {
                u32 b0 = ks[(n*8 + g)*68 + w*8 + tig];
                u32 b1 = ks[(n*8 + g)*68 + w*8 + tig + 4];
                mma16(D[0][n], A[0], b0, b1);
                mma16(D[1][n], A[1], b0, b1);
            }
        }
        {
            const u32* srow = ((w < 4) ? qs : ks) + lane*68 + wq;
            #pragma unroll
            for (int t = 0; t < 4; t++) {
                uint4 vv = *(const uint4*)(srow + t*4);
                float2 a0 = unbf(vv.x), a1 = unbf(vv.y);
                float2 a2 = unbf(vv.z), a3 = unbf(vv.w);
                acc += a0.x*a0.x + a0.y*a0.y + a1.x*a1.x + a1.y*a1.y
                     + a2.x*a2.x + a2.y*a2.y + a3.x*a3.x + a3.y*a3.y;
            }
        }
        __syncthreads();
    }

    ssq[w][lane] = acc;
    float* sred = (float*)qk2;
    #pragma unroll
    for (int m = 0; m < 2; m++)
        #pragma unroll
        for (int n = 0; n < 4; n++) {
            int base = w*1024 + (m*16 + g)*32 + n*8 + 2*tig;
            sred[base]       = D[m][n][0];
            sred[base + 1]   = D[m][n][1];
            sred[base + 256] = D[m][n][2];
            sred[base + 257] = D[m][n][3];
        }
    __syncthreads();

    float* Sp = g_Sp + (((size_t)chunk*BB + b)*NH + h)*1024;
    #pragma unroll
    for (int it = 0; it < 4; it++) {
        int e = tid + it*256;
        float s = 0.f;
        #pragma unroll
        for (int w8 = 0; w8 < 8; w8++) s += sred[w8*1024 + e];
        Sp[e] = s;
    }
    float* sqp = g_sqp + ((size_t)chunk*BB + b)*192;
    if (tid < 32)
        sqp[h*HD + tid] = ssq[0][tid] + ssq[1][tid] + ssq[2][tid] + ssq[3][tid];
    else if (tid < 64) {
        int l = tid - 32;
        sqp[96 + h*HD + l] = ssq[4][l] + ssq[5][l] + ssq[6][l] + ssq[7][l];
    }
}

// ============ K4: softmax (3 warps) + Wp = projW@blockdiag(A) ============
__global__ void __launch_bounds__(256) k4_attn(const float* __restrict__ temp,
                                               const float* __restrict__ projw)
{
    __shared__ float As[NH*1024];
    int b = blockIdx.x;
    int w = threadIdx.x >> 5, lane = threadIdx.x & 31;
    if (w < NH) {
        int h = w;
        float sq = 0.f, sk = 0.f;
        #pragma unroll
        for (int c = 0; c < NCHUNK; c++) {
            const float* sqp = g_sqp + ((size_t)c*BB + b)*192;
            sq += sqp[h*HD + lane];
            sk += sqp[96 + h*HD + lane];
        }
        float nq = fmaxf(sqrtf(sq), 1e-12f);
        float nkv = fmaxf(sqrtf(sk), 1e-12f);
        float tp = temp[h];
        float v[32];
        float mx = 0.f;
        #pragma unroll
        for (int j = 0; j < 32; j++) {
            float nkj = __shfl_sync(0xffffffffu, nkv, j);
            float s = 0.f;
            #pragma unroll
            for (int c = 0; c < NCHUNK; c++)
                s += g_Sp[(((size_t)c*BB + b)*NH + h)*1024 + lane*32 + j];
            s = s / (nq * nkj) * tp;
            s = fmaxf(s, 0.f);
            v[j] = s;
            mx = fmaxf(mx, s);
        }
        float sum = 0.f;
        #pragma unroll
        for (int j = 0; j < 32; j++) { v[j] = expf(v[j] - mx); sum += v[j]; }
        float inv = 1.f / sum;
        #pragma unroll
        for (int j = 0; j < 32; j++)
            As[h*1024 + lane*32 + j] = v[j] * inv;
    }
    __syncthreads();

    int tid = threadIdx.x;
    #pragma unroll 1
    for (int t = 0; t < 18; t++) {
        int widx = tid + t*256;
        int f = widx >> 7, rem = widx & 127;
        int lane2 = rem >> 2, q = rem & 3;
        int mt = f / 6, s = f % 6;
        int g = lane2 >> 2, tig = lane2 & 3;
        int r  = mt*16 + g + (q & 1)*8;
        int kb = s*16 + 2*tig + (q >> 1)*8;
        int h  = kb >> 5, j = kb & 31;
        const float* pw = projw + r*96 + h*32;
        const float* Ab = As + h*1024;
        float w0 = 0.f, w1 = 0.f;
        #pragma unroll
        for (int i = 0; i < 32; i++) {
            float p = pw[i];
            w0 += p * Ab[i*32 + j];
            w1 += p * Ab[i*32 + j + 1];
        }
        g_Wp[(size_t)b*4608 + widx] = packbf(w0, w1);
    }
}

// ============ K5: (Wp@v) + residual + shfl-LN2 + FFN ============
__global__ void __launch_bounds__(256) k5_fused(
    const float* __restrict__ x,
    const float* __restrict__ ln2w,  const float* __restrict__ ln2b,
    const float* __restrict__ projb,
    const float* __restrict__ c1b,   const float* __restrict__ c2b,
    const float* __restrict__ betac, const float* __restrict__ gamma,
    float* __restrict__ out)
{
    extern __shared__ __align__(16) u32 smu[];
    u32* bufA = smu;                 // v -> gated g   (48*SP u32)
    u32* bufB = smu + 48*SP;         // yn             (48*SP u32)
    int b  = blockIdx.x / NPXT;
    int p0 = (blockIdx.x % NPXT) * PXT;
    int tid = threadIdx.x;
    int w = tid >> 5, lane = tid & 31;
    int g = lane >> 2, tig = lane & 3;
    int pxw = w * 16;

    // stage 0: v tile -> bufA via pure cp.async (already ch-pair packed)
    {
        const u32* vbase = g_vp + (size_t)(b*48)*HWP + p0;
        for (int idx = tid; idx < 48*32; idx += 256) {
            int c2 = idx >> 5, q4 = (idx & 31)*4;
            cpa16(s2u(bufA + c2*SP + q4), vbase + (size_t)c2*HWP + q4);
        }
        CPA_COMMIT();
        CPA_WAIT(0);
    }
    __syncthreads();

    // stage 1: y = x + (Wp@v + pb)*betac -> yreg (registers only)
    float yreg[48];
    const u32* wpk = g_Wp + (size_t)b*4608;
    #pragma unroll 1
    for (int mtp = 0; mtp < 3; mtp++) {
        float2 xpre[2][2][2];
        #pragma unroll
        for (int m = 0; m < 2; m++) {
            int r0 = (2*mtp + m)*16 + g;
            #pragma unroll
            for (int n = 0; n < 2; n++) {
                int cl = pxw + n*8 + 2*tig;
                xpre[m][n][0] = *(const float2*)(x + ((size_t)b*CC + r0)*HWP + p0 + cl);
                xpre[m][n][1] = *(const float2*)(x + ((size_t)b*CC + r0 + 8)*HWP + p0 + cl);
            }
        }
        float D[2][2][4];
        #pragma unroll
        for (int m = 0; m < 2; m++)
            #pragma unroll
            for (int n = 0; n < 2; n++)
                #pragma unroll
                for (int c = 0; c < 4; c++) D[m][n][c] = 0.f;
        #pragma unroll
        for (int s = 0; s < 6; s++) {
            u32 A0[4], A1[4];
            ldAb(A0, wpk, (2*mtp)*6 + s, lane);
            ldAb(A1, wpk, (2*mtp + 1)*6 + s, lane);
            u32 b00 = bufA[(8*s + tig)*SP + pxw + g];
            u32 b01 = bufA[(8*s + tig + 4)*SP + pxw + g];
            u32 b10 = bufA[(8*s + tig)*SP + pxw + 8 + g];
            u32 b11 = bufA[(8*s + tig + 4)*SP + pxw + 8 + g];
            mma16(D[0][0], A0, b00, b01); mma16(D[0][1], A0, b10, b11);
            mma16(D[1][0], A1, b00, b01); mma16(D[1][1], A1, b10, b11);
        }
        #pragma unroll
        for (int m = 0; m < 2; m++) {
            int r0 = (2*mtp + m)*16 + g;
            float pb0 = projb[r0], bc0 = betac[r0];
            float pb1 = projb[r0 + 8], bc1 = betac[r0 + 8];
            #pragma unroll
            for (int n = 0; n < 2; n++) {
                int yi = ((mtp*2 + m)*2 + n)*4;
                yreg[yi]   = xpre[m][n][0].x + (D[m][n][0] + pb0)*bc0;
                yreg[yi+1] = xpre[m][n][0].y + (D[m][n][1] + pb0)*bc0;
                yreg[yi+2] = xpre[m][n][1].x + (D[m][n][2] + pb1)*bc1;
                yreg[yi+3] = xpre[m][n][1].y + (D[m][n][3] + pb1)*bc1;
            }
        }
    }

    // LN2 stats via butterfly shuffles over the 8 g-lanes sharing each pixel
    float ps[4]  = {0.f, 0.f, 0.f, 0.f};
    float ps2[4] = {0.f, 0.f, 0.f, 0.f};
    #pragma unroll
    for (int mtp = 0; mtp < 3; mtp++)
        #pragma unroll
        for (int m = 0; m < 2; m++)
            #pragma unroll
            for (int n = 0; n < 2; n++)
                #pragma unroll
                for (int j = 0; j < 2; j++) {
                    int yi = ((mtp*2 + m)*2 + n)*4;
                    int p = n*2 + j;
                    float v0 = yreg[yi + j], v1 = yreg[yi + 2 + j];
                    ps[p]  += v0 + v1;
                    ps2[p] += v0*v0 + v1*v1;
                }
    #pragma unroll
    for (int mask = 4; mask <= 16; mask <<= 1)
        #pragma unroll
        for (int p = 0; p < 4; p++) {
            ps[p]  += __shfl_xor_sync(0xffffffffu, ps[p],  mask);
            ps2[p] += __shfl_xor_sync(0xffffffffu, ps2[p], mask);
        }
    float mu[4], rs[4];
    #pragma unroll
    for (int p = 0; p < 4; p++) {
        mu[p] = ps[p] * (1.0f/96.0f);
        float var = fmaxf(ps2[p] * (1.0f/96.0f) - mu[p]*mu[p], 0.f);
        rs[p] = rsqrtf(var + 1e-6f);
    }
    #pragma unroll
    for (int mtp = 0; mtp < 3; mtp++)
        #pragma unroll
        for (int m = 0; m < 2; m++) {
            int r0 = (2*mtp + m)*16 + g;
            float w0 = ln2w[r0], b0 = ln2b[r0];
            float w1 = ln2w[r0 + 8], b1 = ln2b[r0 + 8];
            #pragma unroll
            for (int n = 0; n < 2; n++)
                #pragma unroll
                for (int j = 0; j < 2; j++) {
                    int yi = ((mtp*2 + m)*2 + n)*4;
                    int p = n*2 + j;
                    int px = pxw + n*8 + 2*tig + j;
                    stbf(bufB, r0,     px, (yreg[yi + j]     - mu[p])*rs[p]*w0 + b0);
                    stbf(bufB, r0 + 8, px, (yreg[yi + 2 + j] - mu[p])*rs[p]*w1 + b1);
                }
        }
    __syncthreads();

    // stage 4: g = (conv1a(yn)+b1)*(conv1b(yn)+b2) -> bufA
    #pragma unroll 1
    for (int mtp = 0; mtp < 3; mtp++) {
        float D1[2][2][4], D2[2][2][4];
        #pragma unroll
        for (int m = 0; m < 2; m++)
            #pragma unroll
            for (int n = 0; n < 2; n++)
                #pragma unroll
                for (int c = 0; c < 4; c++) { D1[m][n][c] = 0.f; D2[m][n][c] = 0.f; }
        #pragma unroll 1
        for (int s = 0; s < 6; s++) {
            u32 A0[4], A1[4], A2[4], A3[4];
            ldAb(A0, g_pk_c1, (2*mtp)*6 + s, lane);
            ldAb(A1, g_pk_c1, (2*mtp + 1)*6 + s, lane);
            ldAb(A2, g_pk_c1, (2*mtp + 6)*6 + s, lane);
            ldAb(A3, g_pk_c1, (2*mtp + 7)*6 + s, lane);
            u32 b00 = bufB[(8*s + tig)*SP + pxw + g];
            u32 b01 = bufB[(8*s + tig + 4)*SP + pxw + g];
            u32 b10 = bufB[(8*s + tig)*SP + pxw + 8 + g];
            u32 b11 = bufB[(8*s + tig + 4)*SP + pxw + 8 + g];
            mma16(D1[0][0], A0, b00, b01); mma16(D1[0][1], A0, b10, b11);
            mma16(D1[1][0], A1, b00, b01); mma16(D1[1][1], A1, b10, b11);
            mma16(D2[0][0], A2, b00, b01); mma16(D2[0][1], A2, b10, b11);
            mma16(D2[1][0], A3, b00, b01); mma16(D2[1][1], A3, b10, b11);
        }
        #pragma unroll
        for (int m = 0; m < 2; m++) {
            int r0 = (2*mtp + m)*16 + g;
            float ba0 = c1b[r0], bb0 = c1b[96 + r0];
            float ba1 = c1b[r0 + 8], bb1 = c1b[96 + r0 + 8];
            #pragma unroll
            for (int n = 0; n < 2; n++) {
                int cl = pxw + n*8 + 2*tig;
                stbf(bufA, r0,     cl,     (D1[m][n][0] + ba0)*(D2[m][n][0] + bb0));
                stbf(bufA, r0,     cl + 1, (D1[m][n][1] + ba0)*(D2[m][n][1] + bb0));
                stbf(bufA, r0 + 8, cl,     (D1[m][n][2] + ba1)*(D2[m][n][2] + bb1));
                stbf(bufA, r0 + 8, cl + 1, (D1[m][n][3] + ba1)*(D2[m][n][3] + bb1));
            }
        }
    }
    __syncthreads();

    // stage 5: out = y + (conv2(g)+cb)*gamma
    #pragma unroll 1
    for (int mtp = 0; mtp < 3; mtp++) {
        float D[2][2][4];
        #pragma unroll
        for (int m = 0; m < 2; m++)
            #pragma unroll
            for (int n = 0; n < 2; n++)
                #pragma unroll
                for (int c = 0; c < 4; c++) D[m][n][c] = 0.f;
        #pragma unroll
        for (int s = 0; s < 6; s++) {
            u32 A0[4], A1[4];
            ldAb(A0, g_pk_c2, (2*mtp)*6 + s, lane);
            ldAb(A1, g_pk_c2, (2*mtp + 1)*6 + s, lane);
            u32 b00 = bufA[(8*s + tig)*SP + pxw + g];
            u32 b01 = bufA[(8*s + tig + 4)*SP + pxw + g];
            u32 b10 = bufA[(8*s + tig)*SP + pxw + 8 + g];
            u32 b11 = bufA[(8*s + tig + 4)*SP + pxw + 8 + g];
            mma16(D[0][0], A0, b00, b01); mma16(D[0][1], A0, b10, b11);
            mma16(D[1][0], A1, b00, b01); mma16(D[1][1], A1, b10, b11);
        }
        #pragma unroll
        for (int m = 0; m < 2; m++) {
            int r0 = (2*mtp + m)*16 + g;
            float cb0 = c2b[r0], gm0 = gamma[r0];
            float cb1 = c2b[r0 + 8], gm1 = gamma[r0 + 8];
            #pragma unroll
            for (int n = 0; n < 2; n++) {
                int cl = pxw + n*8 + 2*tig;
                int yi = ((mtp*2 + m)*2 + n)*4;
                float2 o0, o1;
                o0.x = yreg[yi]   + (D[m][n][0] + cb0)*gm0;
                o0.y = yreg[yi+1] + (D[m][n][1] + cb0)*gm0;
                o1.x = yreg[yi+2] + (D[m][n][2] + cb1)*gm1;
                o1.y = yreg[yi+3] + (D[m][n][3] + cb1)*gm1;
                *(float2*)(out + ((size_t)b*CC + r0)*HWP + p0 + cl) = o0;
                *(float2*)(out + ((size_t)b*CC + r0 + 8)*HWP + p0 + cl) = o1;
            }
        }
    }
}

extern "C" void kernel_launch(void* const* d_in, const int* in_sizes, int n_in,
                              void* d_out, int out_size) {
    (void)in_sizes; (void)n_in; (void)out_size;
    const float* x      = (const float*)d_in[0];
    const float* ln1_w  = (const float*)d_in[1];
    const float* ln1_b  = (const float*)d_in[2];
    const float* ln2_w  = (const float*)d_in[3];
    const float* ln2_b  = (const float*)d_in[4];
    const float* qkv_w  = (const float*)d_in[5];
    const float* qkv_b  = (const float*)d_in[6];
    const float* dw_w   = (const float*)d_in[7];
    const float* dw_b   = (const float*)d_in[8];
    const float* temp   = (const float*)d_in[9];
    const float* proj_w = (const float*)d_in[10];
    const float* proj_b = (const float*)d_in[11];
    const float* c1_w   = (const float*)d_in[12];
    const float* c1_b   = (const float*)d_in[13];
    const float* c2_w   = (const float*)d_in[14];
    const float* c2_b   = (const float*)d_in[15];
    const float* betac  = (const float*)d_in[16];
    const float* gamma  = (const float*)d_in[17];
    float* out = (float*)d_out;

    int smem1 = (48*SP + 2*32*66)*4;  // 43008 B
    int smem3 = 2*4352*4;             // 34816 B
    int smem5 = 96*SP*4;              // 52224 B
    cudaFuncSetAttribute(k1_ln_qkv, cudaFuncAttributeMaxDynamicSharedMemorySize, smem1);
    cudaFuncSetAttribute(k3_gram,   cudaFuncAttributeMaxDynamicSharedMemorySize, smem3);
    cudaFuncSetAttribute(k5_fused,  cudaFuncAttributeMaxDynamicSharedMemorySize, smem5);

    k0_pack<<<126, 256>>>(qkv_w, proj_w, c1_w, c2_w);
    k1_ln_qkv<<<BB*NPXT, 256, smem1>>>(x, ln1_w, ln1_b, qkv_b);
    k2_dw<<<dim3(BB*96 + BB*48, HH/32), 192>>>(dw_w, dw_b);
    k3_gram<<<dim3(BB*NH, NCHUNK), 256, smem3>>>();
    k4_attn<<<BB, 256>>>(temp, proj_w);
    k5_fused<<<BB*NPXT, 256, smem5>>>(x, ln2_w, ln2_b, proj_b,
                                      c1_b, c2_b, betac, gamma, out);
}

// round 17
// speedup vs baseline: 1.0968x; 1.0968x over previous
#include <cuda_runtime.h>
#include <cuda_bf16.h>

#define BB 8
#define CC 96
#define C3 288
#define HH 192
#define WW 192
#define HWP (HH*WW)
#define NH 3
#define HD 32
#define NCHUNK 32
#define CHUNK (HWP/NCHUNK)   // 1152
#define PXT 128
#define NPXT (HWP/PXT)       // 288
#define SP 136               // act smem stride in u32 words (ch-pair rows)

typedef unsigned long long u64;
typedef unsigned int u32;

// ---------------- scratch ----------------
__device__ __nv_bfloat16 g_qkv [(size_t)BB*C3*HWP];   // q,k only (ch 0..191)
__device__ __nv_bfloat16 g_qkvd[(size_t)BB*C3*HWP];   // dw(q,k) (ch 0..191)
__device__ u32   g_vp_in[(size_t)BB*48*HWP];          // v pre-dw, ch-pair packed
__device__ u32   g_vp   [(size_t)BB*48*HWP];          // dw(v), ch-pair packed
__device__ float g_Sp  [NCHUNK*BB*NH*HD*HD];
__device__ float g_sqp [NCHUNK*BB*192];
__device__ u32   g_Wp  [BB*36*128];
__device__ u32 g_pk_qkv [108*128];
__device__ u32 g_pk_proj[36*128];
__device__ u32 g_pk_c1  [72*128];
__device__ u32 g_pk_c2  [36*128];

// ---------------- helpers ----------------
__device__ __forceinline__ void mma16(float d[4], const u32 a[4], u32 b0, u32 b1) {
    asm volatile(
        "mma.sync.aligned.m16n8k16.row.col.f32.bf16.bf16.f32 "
        "{%0,%1,%2,%3},{%4,%5,%6,%7},{%8,%9},{%0,%1,%2,%3};"
        : "+f"(d[0]), "+f"(d[1]), "+f"(d[2]), "+f"(d[3])
        : "r"(a[0]), "r"(a[1]), "r"(a[2]), "r"(a[3]), "r"(b0), "r"(b1));
}
__device__ __forceinline__ void ldAb(u32 a[4], const u32* pk, int frag, int lane) {
    uint4 f = *(const uint4*)(pk + (size_t)frag*128 + lane*4);
    a[0] = f.x; a[1] = f.y; a[2] = f.z; a[3] = f.w;
}
__device__ __forceinline__ u32 packbf(float lo, float hi) {
    __nv_bfloat162 t = __float22bfloat162_rn(make_float2(lo, hi));
    return *reinterpret_cast<u32*>(&t);
}
__device__ __forceinline__ void stbf(u32* buf, int r, int p, float v) {
    reinterpret_cast<__nv_bfloat16*>(buf)[(r >> 1)*(SP*2) + p*2 + (r & 1)] =
        __float2bfloat16(v);
}
__device__ __forceinline__ float2 unbf(u32 wv) {
    __nv_bfloat162 h = *reinterpret_cast<__nv_bfloat162*>(&wv);
    return __bfloat1622float2(h);
}
__device__ __forceinline__ float lobf(u32 v) { return __uint_as_float(v << 16); }
__device__ __forceinline__ float hibf(u32 v) { return __uint_as_float(v & 0xFFFF0000u); }
__device__ __forceinline__ u32 s2u(const void* p) {
    u32 a;
    asm("{ .reg .u64 t; cvta.to.shared.u64 t, %1; cvt.u32.u64 %0, t; }"
        : "=r"(a) : "l"(p));
    return a;
}
__device__ __forceinline__ void cpa16(u32 d, const void* s) {
    asm volatile("cp.async.cg.shared.global [%0], [%1], 16;" :: "r"(d), "l"(s));
}
__device__ __forceinline__ void cpa8(u32 d, const void* s) {
    asm volatile("cp.async.ca.shared.global [%0], [%1], 8;" :: "r"(d), "l"(s));
}
#define CPA_COMMIT() asm volatile("cp.async.commit_group;")
#define CPA_WAIT(n)  asm volatile("cp.async.wait_group %0;" :: "n"(n))

// ============ K0: pack weights into bf16 A-fragment order ============
__global__ void k0_pack(const float* __restrict__ qkvw, const float* __restrict__ projw,
                        const float* __restrict__ c1w,  const float* __restrict__ c2w)
{
    int e = blockIdx.x*256 + threadIdx.x;
    const float* src; u32* dst; int idx = e;
    if      (idx < 13824) { src = qkvw; dst = g_pk_qkv; }
    else if (idx < 18432) { idx -= 13824; src = projw; dst = g_pk_proj; }
    else if (idx < 27648) { idx -= 18432; src = c1w;  dst = g_pk_c1; }
    else if (idx < 32256) { idx -= 27648; src = c2w;  dst = g_pk_c2; }
    else return;
    int f = idx >> 7, rem = idx & 127;
    int lane = rem >> 2, q = rem & 3;
    int mt = f / 6, s = f % 6;
    int g = lane >> 2, tig = lane & 3;
    int r  = mt*16 + g + (q & 1)*8;
    int kb = s*16 + 2*tig + (q >> 1)*8;
    dst[idx] = packbf(src[r*96 + kb], src[r*96 + kb + 1]);
}

// ============ K1: LN1 + qkv (bf16 mma; q,k normal, v packed ch-pair) ============
__global__ void __launch_bounds__(256) k1_ln_qkv(
    const float* __restrict__ x,    const float* __restrict__ ln1w,
    const float* __restrict__ ln1b, const float* __restrict__ qkvb)
{
    extern __shared__ __align__(16) u32 smu[];   // 48*SP input + 2 x 32*66 staging
    u32* stg = smu + 48*SP;
    int b  = blockIdx.x / NPXT;
    int p0 = (blockIdx.x % NPXT) * PXT;
    int tid = threadIdx.x;

    const float* xb = x + (size_t)b*CC*HWP + p0;
    for (int idx = tid; idx < 48*32; idx += 256) {
        int c2 = idx >> 5, p4 = (idx & 31)*4;
        float4 v0 = __ldcs((const float4*)(xb + (size_t)(2*c2)*HWP + p4));
        float4 v1 = __ldcs((const float4*)(xb + (size_t)(2*c2 + 1)*HWP + p4));
        smu[c2*SP + p4 + 0] = packbf(v0.x, v1.x);
        smu[c2*SP + p4 + 1] = packbf(v0.y, v1.y);
        smu[c2*SP + p4 + 2] = packbf(v0.z, v1.z);
        smu[c2*SP + p4 + 3] = packbf(v0.w, v1.w);
    }
    __syncthreads();
    {
        int px = tid >> 1, half = tid & 1;
        int c20 = half * 24;
        float s = 0.f, s2 = 0.f;
        #pragma unroll
        for (int c2 = c20; c2 < c20 + 24; c2++) {
            float2 f = unbf(smu[c2*SP + px]);
            s += f.x + f.y; s2 += f.x*f.x + f.y*f.y;
        }
        s  += __shfl_xor_sync(0xffffffffu, s, 1);
        s2 += __shfl_xor_sync(0xffffffffu, s2, 1);
        float mu  = s * (1.0f/96.0f);
        float var = fmaxf(s2 * (1.0f/96.0f) - mu*mu, 0.f);
        float rs  = rsqrtf(var + 1e-6f);
        #pragma unroll
        for (int c2 = c20; c2 < c20 + 24; c2++) {
            float2 f = unbf(smu[c2*SP + px]);
            float y0 = (f.x - mu)*rs*ln1w[2*c2]   + ln1b[2*c2];
            float y1 = (f.y - mu)*rs*ln1w[2*c2+1] + ln1b[2*c2+1];
            smu[c2*SP + px] = packbf(y0, y1);
        }
    }
    __syncthreads();

    int w = tid >> 5, lane = tid & 31;
    int g = lane >> 2, tig = lane & 3;
    int pxw = w * 16;
    #pragma unroll 1
    for (int mtp = 0; mtp < 9; mtp++) {
        u32* stgp = stg + (mtp & 1)*(32*66);
        float D[2][2][4];
        #pragma unroll
        for (int m = 0; m < 2; m++)
            #pragma unroll
            for (int n = 0; n < 2; n++)
                #pragma unroll
                for (int c = 0; c < 4; c++) D[m][n][c] = 0.f;
        #pragma unroll
        for (int s = 0; s < 6; s++) {
            u32 A0[4], A1[4];
            ldAb(A0, g_pk_qkv, (2*mtp)*6 + s, lane);
            ldAb(A1, g_pk_qkv, (2*mtp + 1)*6 + s, lane);
            u32 b00 = smu[(8*s + tig)*SP + pxw + g];
            u32 b01 = smu[(8*s + tig + 4)*SP + pxw + g];
            u32 b10 = smu[(8*s + tig)*SP + pxw + 8 + g];
            u32 b11 = smu[(8*s + tig + 4)*SP + pxw + 8 + g];
            mma16(D[0][0], A0, b00, b01); mma16(D[0][1], A0, b10, b11);
            mma16(D[1][0], A1, b00, b01); mma16(D[1][1], A1, b10, b11);
        }
        #pragma unroll
        for (int m = 0; m < 2; m++) {
            int r0 = (2*mtp + m)*16 + g;
            int lr = m*16 + g;
            float bz0 = qkvb[r0], bz1 = qkvb[r0 + 8];
            #pragma unroll
            for (int n = 0; n < 2; n++) {
                int cw = (pxw >> 1) + n*4 + tig;
                stgp[lr*66 + cw]       = packbf(D[m][n][0] + bz0, D[m][n][1] + bz0);
                stgp[(lr + 8)*66 + cw] = packbf(D[m][n][2] + bz1, D[m][n][3] + bz1);
            }
        }
        __syncthreads();
        if (mtp < 6) {
            int rowbase = mtp*32;
            #pragma unroll
            for (int it = 0; it < 4; it++) {
                int idx = tid + it*256;
                int r = idx >> 5, cw2 = (idx & 31) * 2;
                *(uint2*)((u32*)(g_qkv + ((size_t)b*C3 + rowbase + r)*HWP + p0) + cw2) =
                    *(const uint2*)(stgp + r*66 + cw2);
            }
        } else {
            int c2base = (mtp - 6)*16;
            #pragma unroll
            for (int it = 0; it < 4; it++) {
                int idx = tid + it*256;
                int a = idx >> 6, j2 = idx & 63;
                u32 w0 = stgp[(2*a)*66 + j2];
                u32 w1 = stgp[(2*a + 1)*66 + j2];
                uint2 o;
                o.x = __byte_perm(w0, w1, 0x5410);
                o.y = __byte_perm(w0, w1, 0x7632);
                *(uint2*)(g_vp_in + ((size_t)(b*48 + c2base + a))*HWP + p0 + 2*j2) = o;
            }
        }
    }
}

// ============ K2: merged depthwise 3x3 (q,k path + packed-v path) ============
__global__ void __launch_bounds__(192) k2_dw(const float* __restrict__ dww,
                                             const float* __restrict__ dwb)
{
    __shared__ u32 sm2[2*34*100];   // qk: [cc][34][100]; v uses [34][196]
    int bx = blockIdx.x;
    int y0 = blockIdx.y * 32;
    int tid = threadIdx.x;

    if (bx < BB*96) {
        // ---- q,k path (round-15 body verbatim) ----
        int b = bx / 96, chp = bx % 96;
        int ch0 = 2*chp;
        int half = tid / 96, t = tid % 96;
        for (int idx = tid; idx < 2*34*48; idx += 192) {
            int cc = idx / 1632, rem = idx % 1632;
            int r = rem / 48, q2 = rem % 48;
            int y = y0 - 1 + r;
            u32* dsts = sm2 + cc*3400 + r*100 + q2*2;
            if (y >= 0 && y < HH) {
                const __nv_bfloat16* in = g_qkv + ((size_t)b*C3 + ch0 + cc)*HWP;
                cpa8(s2u(dsts), (const u32*)(in + y*WW) + q2*2);
            } else {
                dsts[0] = 0u; dsts[1] = 0u;
            }
        }
        CPA_COMMIT();
        CPA_WAIT(0);
        __syncthreads();

        int ch = ch0 + half;
        float w[9];
        #pragma unroll
        for (int q = 0; q < 9; q++) w[q] = dww[ch*9 + q];
        float bias = dwb[ch];
        u32* outw = (u32*)(g_qkvd + ((size_t)b*C3 + ch)*HWP);
        const u32* base = sm2 + half*3400;
        bool hasL = (t > 0), hasR = (t < 95);

        float a[3], bb[3], c[3], d[3];
        #pragma unroll
        for (int r = 0; r < 2; r++) {
            const u32* rowp = base + r*100;
            u32 wp = hasL ? rowp[t-1] : 0u;
            u32 wm = rowp[t];
            u32 wn = hasR ? rowp[t+1] : 0u;
            a[r] = hibf(wp); bb[r] = lobf(wm); c[r] = hibf(wm); d[r] = lobf(wn);
        }
        #pragma unroll
        for (int ry = 0; ry < 32; ry++) {
            int s2 = (ry + 2) % 3;
            {
                const u32* rowp = base + (ry + 2)*100;
                u32 wp = hasL ? rowp[t-1] : 0u;
                u32 wm = rowp[t];
                u32 wn = hasR ? rowp[t+1] : 0u;
                a[s2] = hibf(wp); bb[s2] = lobf(wm); c[s2] = hibf(wm); d[s2] = lobf(wn);
            }
            int s0 = ry % 3, s1 = (ry + 1) % 3;
            float o0 = bias
                + w[0]*a[s0]  + w[1]*bb[s0] + w[2]*c[s0]
                + w[3]*a[s1]  + w[4]*bb[s1] + w[5]*c[s1]
                + w[6]*a[s2]  + w[7]*bb[s2] + w[8]*c[s2];
            float o1 = bias
                + w[0]*bb[s0] + w[1]*c[s0]  + w[2]*d[s0]
                + w[3]*bb[s1] + w[4]*c[s1]  + w[5]*d[s1]
                + w[6]*bb[s2] + w[7]*c[s2]  + w[8]*d[s2];
            outw[(y0 + ry)*96 + t] = packbf(o0, o1);
        }
    } else {
        // ---- v path (round-15 body verbatim) ----
        int vx = bx - BB*96;
        int b = vx / 48, c2 = vx % 48;
        const u32* inw = g_vp_in + (size_t)(b*48 + c2)*HWP;
        for (int idx = tid; idx < 34*96; idx += 192) {
            int r = idx / 96, q2 = idx % 96;
            int y = y0 - 1 + r;
            u32* d = sm2 + r*196 + q2*2;
            if (y >= 0 && y < HH) cpa8(s2u(d), inw + y*WW + q2*2);
            else { d[0] = 0u; d[1] = 0u; }
        }
        CPA_COMMIT();
        CPA_WAIT(0);
        __syncthreads();

        int ch0 = 192 + 2*c2;
        float w0[9], w1[9];
        #pragma unroll
        for (int q = 0; q < 9; q++) { w0[q] = dww[ch0*9 + q]; w1[q] = dww[(ch0+1)*9 + q]; }
        float b0 = dwb[ch0], b1 = dwb[ch0 + 1];
        u32* outw = g_vp + (size_t)(b*48 + c2)*HWP;
        int t = tid;
        bool hasL = (t > 0), hasR = (t < WW - 1);

        float l0[3], m0[3], n0[3], l1[3], m1[3], n1[3];
        #pragma unroll
        for (int r = 0; r < 2; r++) {
            const u32* rp = sm2 + r*196;
            u32 wl = hasL ? rp[t-1] : 0u;
            u32 wm = rp[t];
            u32 wn = hasR ? rp[t+1] : 0u;
            l0[r] = lobf(wl); m0[r] = lobf(wm); n0[r] = lobf(wn);
            l1[r] = hibf(wl); m1[r] = hibf(wm); n1[r] = hibf(wn);
        }
        #pragma unroll
        for (int ry = 0; ry < 32; ry++) {
            int s2 = (ry + 2) % 3;
            {
                const u32* rp = sm2 + (ry + 2)*196;
                u32 wl = hasL ? rp[t-1] : 0u;
                u32 wm = rp[t];
                u32 wn = hasR ? rp[t+1] : 0u;
                l0[s2] = lobf(wl); m0[s2] = lobf(wm); n0[s2] = lobf(wn);
                l1[s2] = hibf(wl); m1[s2] = hibf(wm); n1[s2] = hibf(wn);
            }
            int s0 = ry % 3, s1 = (ry + 1) % 3;
            float o0 = b0
                + w0[0]*l0[s0] + w0[1]*m0[s0] + w0[2]*n0[s0]
                + w0[3]*l0[s1] + w0[4]*m0[s1] + w0[5]*n0[s1]
                + w0[6]*l0[s2] + w0[7]*m0[s2] + w0[8]*n0[s2];
            float o1 = b1
                + w1[0]*l1[s0] + w1[1]*m1[s0] + w1[2]*n1[s0]
                + w1[3]*l1[s1] + w1[4]*m1[s1] + w1[5]*n1[s1]
                + w1[6]*l1[s2] + w1[7]*m1[s2] + w1[8]*n1[s2];
            outw[(y0 + ry)*WW + t] = packbf(o0, o1);
        }
    }
}

// ============ K3: Gram + sumsq, bf16 mma, cp.async double-buffered ============
__global__ void __launch_bounds__(256) k3_gram()
{
    extern __shared__ __align__(16) u32 qk2[];
    __shared__ float ssq[8][32];
    int bh = blockIdx.x, chunk = blockIdx.y;
    int b = bh / NH, h = bh % NH;
    int tid = threadIdx.x;
    int w = tid >> 5, lane = tid & 31;
    int g = lane >> 2, tig = lane & 3;
    const __nv_bfloat16* qbase = g_qkvd + ((size_t)b*C3 + h*HD)*HWP + chunk*CHUNK;
    const __nv_bfloat16* kbase = g_qkvd + ((size_t)b*C3 + 96 + h*HD)*HWP + chunk*CHUNK;

    float D[2][4][4];
    #pragma unroll
    for (int m = 0; m < 2; m++)
        #pragma unroll
        for (int n = 0; n < 4; n++)
            #pragma unroll
            for (int c = 0; c < 4; c++) D[m][n][c] = 0.f;
    float acc = 0.f;
    int wq = (w & 3) * 16;

    {
        #pragma unroll
        for (int it = 0; it < 2; it++) {
            int idx = tid + it*256;
            int ci = idx >> 4, w4 = (idx & 15)*4;
            cpa16(s2u(qk2 + ci*68 + w4),
                  (const u32*)(qbase + (size_t)ci*HWP) + w4);
            cpa16(s2u(qk2 + 2176 + ci*68 + w4),
                  (const u32*)(kbase + (size_t)ci*HWP) + w4);
        }
        CPA_COMMIT();
    }

    #pragma unroll 1
    for (int st = 0; st < 9; st++) {
        u32* cur = qk2 + (st & 1)*4352;
        if (st < 8) {
            u32* nxt = qk2 + ((st + 1) & 1)*4352;
            int poff = (st + 1)*128;
            #pragma unroll
            for (int it = 0; it < 2; it++) {
                int idx = tid + it*256;
                int ci = idx >> 4, w4 = (idx & 15)*4;
                cpa16(s2u(nxt + ci*68 + w4),
                      (const u32*)(qbase + (size_t)ci*HWP + poff) + w4);
                cpa16(s2u(nxt + 2176 + ci*68 + w4),
                      (const u32*)(kbase + (size_t)ci*HWP + poff) + w4);
            }
            CPA_COMMIT();
            CPA_WAIT(1);
        } else {
            CPA_WAIT(0);
        }
        __syncthreads();
        u32* qs = cur;
        u32* ks = cur + 2176;
        {
            u32 A[2][4];
            #pragma unroll
            for (int m = 0; m < 2; m++) {
                A[m][0] = qs[(m*16 + g)*68     + w*8 + tig];
                A[m][1] = qs[(m*16 + g + 8)*68 + w*8 + tig];
                A[m][2] = qs[(m*16 + g)*68     + w*8 + tig + 4];
                A[m][3] = qs[(m*16 + g + 8)*68 + w*8 + tig + 4];
            }
            #pragma unroll
            for (int n = 0; n < 4; n++) {
                u32 b0 = ks[(n*8 + g)*68 + w*8 + tig];
                u32 b1 = ks[(n*8 + g)*68 + w*8 + tig + 4];
                mma16(D[0][n], A[0], b0, b1);
                mma16(D[1][n], A[1], b0, b1);
            }
        }
        {
            const u32* srow = ((w < 4) ? qs : ks) + lane*68 + wq;
            #pragma unroll
            for (int t = 0; t < 4; t++) {
                uint4 vv = *(const uint4*)(srow + t*4);
                float2 a0 = unbf(vv.x), a1 = unbf(vv.y);
                float2 a2 = unbf(vv.z), a3 = unbf(vv.w);
                acc += a0.x*a0.x + a0.y*a0.y + a1.x*a1.x + a1.y*a1.y
                     + a2.x*a2.x + a2.y*a2.y + a3.x*a3.x + a3.y*a3.y;
            }
        }
        __syncthreads();
    }

    ssq[w][lane] = acc;
    float* sred = (float*)qk2;
    #pragma unroll
    for (int m = 0; m < 2; m++)
        #pragma unroll
        for (int n = 0; n < 4; n++) {
            int base = w*1024 + (m*16 + g)*32 + n*8 + 2*tig;
            sred[base]       = D[m][n][0];
            sred[base + 1]   = D[m][n][1];
            sred[base + 256] = D[m][n][2];
            sred[base + 257] = D[m][n][3];
        }
    __syncthreads();

    float* Sp = g_Sp + (((size_t)chunk*BB + b)*NH + h)*1024;
    #pragma unroll
    for (int it = 0; it < 4; it++) {
        int e = tid + it*256;
        float s = 0.f;
        #pragma unroll
        for (int w8 = 0; w8 < 8; w8++) s += sred[w8*1024 + e];
        Sp[e] = s;
    }
    float* sqp = g_sqp + ((size_t)chunk*BB + b)*192;
    if (tid < 32)
        sqp[h*HD + tid] = ssq[0][tid] + ssq[1][tid] + ssq[2][tid] + ssq[3][tid];
    else if (tid < 64) {
        int l = tid - 32;
        sqp[96 + h*HD + l] = ssq[4][l] + ssq[5][l] + ssq[6][l] + ssq[7][l];
    }
}

// ============ K4: per-(b,h) softmax + Wp slice (grid 24) ============
__global__ void __launch_bounds__(256) k4_attn(const float* __restrict__ temp,
                                               const float* __restrict__ projw)
{
    __shared__ float As[1024];
    int b = blockIdx.x / NH, h = blockIdx.x % NH;
    int w = threadIdx.x >> 5, lane = threadIdx.x & 31;
    if (w == 0) {
        float sq = 0.f, sk = 0.f;
        #pragma unroll
        for (int c = 0; c < NCHUNK; c++) {
            const float* sqp = g_sqp + ((size_t)c*BB + b)*192;
            sq += sqp[h*HD + lane];
            sk += sqp[96 + h*HD + lane];
        }
        float nq = fmaxf(sqrtf(sq), 1e-12f);
        float nkv = fmaxf(sqrtf(sk), 1e-12f);
        float tp = temp[h];
        float v[32];
        float mx = 0.f;
        #pragma unroll
        for (int j = 0; j < 32; j++) {
            float nkj = __shfl_sync(0xffffffffu, nkv, j);
            float s = 0.f;
            #pragma unroll
            for (int c = 0; c < NCHUNK; c++)
                s += g_Sp[(((size_t)c*BB + b)*NH + h)*1024 + lane*32 + j];
            s = s / (nq * nkj) * tp;
            s = fmaxf(s, 0.f);
            v[j] = s;
            mx = fmaxf(mx, s);
        }
        float sum = 0.f;
        #pragma unroll
        for (int j = 0; j < 32; j++) { v[j] = expf(v[j] - mx); sum += v[j]; }
        float inv = 1.f / sum;
        #pragma unroll
        for (int j = 0; j < 32; j++)
            As[lane*32 + j] = v[j] * inv;
    }
    __syncthreads();

    // Wp slice: s in {2h, 2h+1} -> 12 frags x 128 = 1536 elements
    int tid = threadIdx.x;
    #pragma unroll 1
    for (int t = 0; t < 6; t++) {
        int idx = tid + t*256;               // 0..1535
        int fp = idx >> 7, rem = idx & 127;
        int mt = fp >> 1, ss = fp & 1;
        int s = 2*h + ss;
        int lane2 = rem >> 2, q = rem & 3;
        int g = lane2 >> 2, tig = lane2 & 3;
        int r  = mt*16 + g + (q & 1)*8;
        int j  = ss*16 + 2*tig + (q >> 1)*8;  // kb - 32h
        const float* pw = projw + r*96 + h*32;
        float w0 = 0.f, w1 = 0.f;
        #pragma unroll
        for (int i = 0; i < 32; i++) {
            float p = pw[i];
            w0 += p * As[i*32 + j];
            w1 += p * As[i*32 + j + 1];
        }
        int widx = (mt*6 + s)*128 + rem;
        g_Wp[(size_t)b*4608 + widx] = packbf(w0, w1);
    }
}

// ============ K5: (Wp@v) + residual + shfl-LN2 + FFN ============
__global__ void __launch_bounds__(256) k5_fused(
    const float* __restrict__ x,
    const float* __restrict__ ln2w,  const float* __restrict__ ln2b,
    const float* __restrict__ projb,
    const float* __restrict__ c1b,   const float* __restrict__ c2b,
    const float* __restrict__ betac, const float* __restrict__ gamma,
    float* __restrict__ out)
{
    extern __shared__ __align__(16) u32 smu[];
    u32* bufA = smu;                 // v -> gated g   (48*SP u32)
    u32* bufB = smu + 48*SP;         // yn             (48*SP u32)
    int b  = blockIdx.x / NPXT;
    int p0 = (blockIdx.x % NPXT) * PXT;
    int tid = threadIdx.x;
    int w = tid >> 5, lane = tid & 31;
    int g = lane >> 2, tig = lane & 3;
    int pxw = w * 16;

    // stage 0: v tile -> bufA via pure cp.async (already ch-pair packed)
    {
        const u32* vbase = g_vp + (size_t)(b*48)*HWP + p0;
        for (int idx = tid; idx < 48*32; idx += 256) {
            int c2 = idx >> 5, q4 = (idx & 31)*4;
            cpa16(s2u(bufA + c2*SP + q4), vbase + (size_t)c2*HWP + q4);
        }
        CPA_COMMIT();
        CPA_WAIT(0);
    }
    __syncthreads();

    // stage 1: y = x + (Wp@v + pb)*betac -> yreg (registers only)
    float yreg[48];
    const u32* wpk = g_Wp + (size_t)b*4608;
    #pragma unroll 1
    for (int mtp = 0; mtp < 3; mtp++) {
        float2 xpre[2][2][2];
        #pragma unroll
        for (int m = 0; m < 2; m++) {
            int r0 = (2*mtp + m)*16 + g;
            #pragma unroll
            for (int n = 0; n < 2; n++) {
                int cl = pxw + n*8 + 2*tig;
                xpre[m][n][0] = __ldcs((const float2*)(x + ((size_t)b*CC + r0)*HWP + p0 + cl));
                xpre[m][n][1] = __ldcs((const float2*)(x + ((size_t)b*CC + r0 + 8)*HWP + p0 + cl));
            }
        }
        float D[2][2][4];
        #pragma unroll
        for (int m = 0; m < 2; m++)
            #pragma unroll
            for (int n = 0; n < 2; n++)
                #pragma unroll
                for (int c = 0; c < 4; c++) D[m][n][c] = 0.f;
        #pragma unroll
        for (int s = 0; s < 6; s++) {
            u32 A0[4], A1[4];
            ldAb(A0, wpk, (2*mtp)*6 + s, lane);
            ldAb(A1, wpk, (2*mtp + 1)*6 + s, lane);
            u32 b00 = bufA[(8*s + tig)*SP + pxw + g];
            u32 b01 = bufA[(8*s + tig + 4)*SP + pxw + g];
            u32 b10 = bufA[(8*s + tig)*SP + pxw + 8 + g];
            u32 b11 = bufA[(8*s + tig + 4)*SP + pxw + 8 + g];
            mma16(D[0][0], A0, b00, b01); mma16(D[0][1], A0, b10, b11);
            mma16(D[1][0], A1, b00, b01); mma16(D[1][1], A1, b10, b11);
        }
        #pragma unroll
        for (int m = 0; m < 2; m++) {
            int r0 = (2*mtp + m)*16 + g;
            float pb0 = projb[r0], bc0 = betac[r0];
            float pb1 = projb[r0 + 8], bc1 = betac[r0 + 8];
            #pragma unroll
            for (int n = 0; n < 2; n++) {
                int yi = ((mtp*2 + m)*2 + n)*4;
                yreg[yi]   = xpre[m][n][0].x + (D[m][n][0] + pb0)*bc0;
                yreg[yi+1] = xpre[m][n][0].y + (D[m][n][1] + pb0)*bc0;
                yreg[yi+2] = xpre[m][n][1].x + (D[m][n][2] + pb1)*bc1;
                yreg[yi+3] = xpre[m][n][1].y + (D[m][n][3] + pb1)*bc1;
            }
        }
    }

    // LN2 stats via butterfly shuffles over the 8 g-lanes sharing each pixel
    float ps[4]  = {0.f, 0.f, 0.f, 0.f};
    float ps2[4] = {0.f, 0.f, 0.f, 0.f};
    #pragma unroll
    for (int mtp = 0; mtp < 3; mtp++)
        #pragma unroll
        for (int m = 0; m < 2; m++)
            #pragma unroll
            for (int n = 0; n < 2; n++)
                #pragma unroll
                for (int j = 0; j < 2; j++) {
                    int yi = ((mtp*2 + m)*2 + n)*4;
                    int p = n*2 + j;
                    float v0 = yreg[yi + j], v1 = yreg[yi + 2 + j];
                    ps[p]  += v0 + v1;
                    ps2[p] += v0*v0 + v1*v1;
                }
    #pragma unroll
    for (int mask = 4; mask <= 16; mask <<= 1)
        #pragma unroll
        for (int p = 0; p < 4; p++) {
            ps[p]  += __shfl_xor_sync(0xffffffffu, ps[p],  mask);
            ps2[p] += __shfl_xor_sync(0xffffffffu, ps2[p], mask);
        }
    float mu[4], rs[4];
    #pragma unroll
    for (int p = 0; p < 4; p++) {
        mu[p] = ps[p] * (1.0f/96.0f);
        float var = fmaxf(ps2[p] * (1.0f/96.0f) - mu[p]*mu[p], 0.f);
        rs[p] = rsqrtf(var + 1e-6f);
    }
    #pragma unroll
    for (int mtp = 0; mtp < 3; mtp++)
        #pragma unroll
        for (int m = 0; m < 2; m++) {
            int r0 = (2*mtp + m)*16 + g;
            float w0 = ln2w[r0], b0 = ln2b[r0];
            float w1 = ln2w[r0 + 8], b1 = ln2b[r0 + 8];
            #pragma unroll
            for (int n = 0; n < 2; n++)
                #pragma unroll
                for (int j = 0; j < 2; j++) {
                    int yi = ((mtp*2 + m)*2 + n)*4;
                    int p = n*2 + j;
                    int px = pxw + n*8 + 2*tig + j;
                    stbf(bufB, r0,     px, (yreg[yi + j]     - mu[p])*rs[p]*w0 + b0);
                    stbf(bufB, r0 + 8, px, (yreg[yi + 2 + j] - mu[p])*rs[p]*w1 + b1);
                }
        }
    __syncthreads();

    // stage 4: g = (conv1a(yn)+b1)*(conv1b(yn)+b2) -> bufA
    #pragma unroll 1
    for (int mtp = 0; mtp < 3; mtp++) {
        float D1[2][2][4], D2[2][2][4];
        #pragma unroll
        for (int m = 0; m < 2; m++)
            #pragma unroll
            for (int n = 0; n < 2; n++)
                #pragma unroll
                for (int c = 0; c < 4; c++) { D1[m][n][c] = 0.f; D2[m][n][c] = 0.f; }
        #pragma unroll 1
        for (int s = 0; s < 6; s++) {
            u32 A0[4], A1[4], A2[4], A3[4];
            ldAb(A0, g_pk_c1, (2*mtp)*6 + s, lane);
            ldAb(A1, g_pk_c1, (2*mtp + 1)*6 + s, lane);
            ldAb(A2, g_pk_c1, (2*mtp + 6)*6 + s, lane);
            ldAb(A3, g_pk_c1, (2*mtp + 7)*6 + s, lane);
            u32 b00 = bufB[(8*s + tig)*SP + pxw + g];
            u32 b01 = bufB[(8*s + tig + 4)*SP + pxw + g];
            u32 b10 = bufB[(8*s + tig)*SP + pxw + 8 + g];
            u32 b11 = bufB[(8*s + tig + 4)*SP + pxw + 8 + g];
            mma16(D1[0][0], A0, b00, b01); mma16(D1[0][1], A0, b10, b11);
            mma16(D1[1][0], A1, b00, b01); mma16(D1[1][1], A1, b10, b11);
            mma16(D2[0][0], A2, b00, b01); mma16(D2[0][1], A2, b10, b11);
            mma16(D2[1][0], A3, b00, b01); mma16(D2[1][1], A3, b10, b11);
        }
        #pragma unroll
        for (int m = 0; m < 2; m++) {
            int r0 = (2*mtp + m)*16 + g;
            float ba0 = c1b[r0], bb0 = c1b[96 + r0];
            float ba1 = c1b[r0 + 8], bb1 = c1b[96 + r0 + 8];
            #pragma unroll
            for (int n = 0; n < 2; n++) {
                int cl = pxw + n*8 + 2*tig;
                stbf(bufA, r0,     cl,     (D1[m][n][0] + ba0)*(D2[m][n][0] + bb0));
                stbf(bufA, r0,     cl + 1, (D1[m][n][1] + ba0)*(D2[m][n][1] + bb0));
                stbf(bufA, r0 + 8, cl,     (D1[m][n][2] + ba1)*(D2[m][n][2] + bb1));
                stbf(bufA, r0 + 8, cl + 1, (D1[m][n][3] + ba1)*(D2[m][n][3] + bb1));
            }
        }
    }
    __syncthreads();

    // stage 5: out = y + (conv2(g)+cb)*gamma
    #pragma unroll 1
    for (int mtp = 0; mtp < 3; mtp++) {
        float D[2][2][4];
        #pragma unroll
        for (int m = 0; m < 2; m++)
            #pragma unroll
            for (int n = 0; n < 2; n++)
                #pragma unroll
                for (int c = 0; c < 4; c++) D[m][n][c] = 0.f;
        #pragma unroll
        for (int s = 0; s < 6; s++) {
            u32 A0[4], A1[4];
            ldAb(A0, g_pk_c2, (2*mtp)*6 + s, lane);
            ldAb(A1, g_pk_c2, (2*mtp + 1)*6 + s, lane);
            u32 b00 = bufA[(8*s + tig)*SP + pxw + g];
            u32 b01 = bufA[(8*s + tig + 4)*SP + pxw + g];
            u32 b10 = bufA[(8*s + tig)*SP + pxw + 8 + g];
            u32 b11 = bufA[(8*s + tig + 4)*SP + pxw + 8 + g];
            mma16(D[0][0], A0, b00, b01); mma16(D[0][1], A0, b10, b11);
            mma16(D[1][0], A1, b00, b01); mma16(D[1][1], A1, b10, b11);
        }
        #pragma unroll
        for (int m = 0; m < 2; m++) {
            int r0 = (2*mtp + m)*16 + g;
            float cb0 = c2b[r0], gm0 = gamma[r0];
            float cb1 = c2b[r0 + 8], gm1 = gamma[r0 + 8];
            #pragma unroll
            for (int n = 0; n < 2; n++) {
                int cl = pxw + n*8 + 2*tig;
                int yi = ((mtp*2 + m)*2 + n)*4;
                float2 o0, o1;
                o0.x = yreg[yi]   + (D[m][n][0] + cb0)*gm0;
                o0.y = yreg[yi+1] + (D[m][n][1] + cb0)*gm0;
                o1.x = yreg[yi+2] + (D[m][n][2] + cb1)*gm1;
                o1.y = yreg[yi+3] + (D[m][n][3] + cb1)*gm1;
                *(float2*)(out + ((size_t)b*CC + r0)*HWP + p0 + cl) = o0;
                *(float2*)(out + ((size_t)b*CC + r0 + 8)*HWP + p0 + cl) = o1;
            }
        }
    }
}

extern "C" void kernel_launch(void* const* d_in, const int* in_sizes, int n_in,
                              void* d_out, int out_size) {
    (void)in_sizes; (void)n_in; (void)out_size;
    const float* x      = (const float*)d_in[0];
    const float* ln1_w  = (const float*)d_in[1];
    const float* ln1_b  = (const float*)d_in[2];
    const float* ln2_w  = (const float*)d_in[3];
    const float* ln2_b  = (const float*)d_in[4];
    const float* qkv_w  = (const float*)d_in[5];
    const float* qkv_b  = (const float*)d_in[6];
    const float* dw_w   = (const float*)d_in[7];
    const float* dw_b   = (const float*)d_in[8];
    const float* temp   = (const float*)d_in[9];
    const float* proj_w = (const float*)d_in[10];
    const float* proj_b = (const float*)d_in[11];
    const float* c1_w   = (const float*)d_in[12];
    const float* c1_b   = (const float*)d_in[13];
    const float* c2_w   = (const float*)d_in[14];
    const float* c2_b   = (const float*)d_in[15];
    const float* betac  = (const float*)d_in[16];
    const float* gamma  = (const float*)d_in[17];
    float* out = (float*)d_out;

    int smem1 = (48*SP + 2*32*66)*4;  // 43008 B
    int smem3 = 2*4352*4;             // 34816 B
    int smem5 = 96*SP*4;              // 52224 B
    cudaFuncSetAttribute(k1_ln_qkv, cudaFuncAttributeMaxDynamicSharedMemorySize, smem1);
    cudaFuncSetAttribute(k3_gram,   cudaFuncAttributeMaxDynamicSharedMemorySize, smem3);
    cudaFuncSetAttribute(k5_fused,  cudaFuncAttributeMaxDynamicSharedMemorySize, smem5);

    k0_pack<<<126, 256>>>(qkv_w, proj_w, c1_w, c2_w);
    k1_ln_qkv<<<BB*NPXT, 256, smem1>>>(x, ln1_w, ln1_b, qkv_b);
    k2_dw<<<dim3(BB*96 + BB*48, HH/32), 192>>>(dw_w, dw_b);
    k3_gram<<<dim3(BB*NH, NCHUNK), 256, smem3>>>();
    k4_attn<<<BB*NH, 256>>>(temp, proj_w);
    k5_fused<<<BB*NPXT, 256, smem5>>>(x, ln2_w, ln2_b, proj_b,
                                      c1_b, c2_b, betac, gamma, out);
}